// round 5
// baseline (speedup 1.0000x reference)
#include <cuda_runtime.h>

#define SIZE 512
#define NS 256
#define BX 16
#define BY 8
#define NT 128
#define K2ST 132                     // keep2 stride in float4 (264 float2)

__device__ float4 g_samples4[NS / 2];   // 256 float2 samples, 16B-aligned

__device__ __forceinline__ float fsqrt_approx(float x) {
    float r; asm("sqrt.approx.f32 %0, %1;" : "=f"(r) : "f"(x)); return r;
}
__device__ __forceinline__ float fexp2_approx(float x) {
    float r; asm("ex2.approx.f32 %0, %1;" : "=f"(r) : "f"(x)); return r;
}
__device__ __forceinline__ float flog2_approx(float x) {
    float r; asm("lg2.approx.f32 %0, %1;" : "=f"(r) : "f"(x)); return r;
}

// ---- setup: compute the 256 clamped Bezier samples once ----
__global__ void sample_kernel(const float* __restrict__ cp) {
    const int tid = threadIdx.x;          // 0..255
    const int stroke = tid >> 5;
    const int j = tid & 31;
    const float t  = (float)j * (1.0f / 31.0f);
    const float mt = 1.0f - t;
    const float* c = cp + stroke * 8;
    const float w0 = mt * mt * mt;
    const float w1 = 3.0f * mt * mt * t;
    const float w2 = 3.0f * mt * t * t;
    const float w3 = t * t * t;
    const float sx = w0 * __saturatef(c[0]) + w1 * __saturatef(c[2])
                   + w2 * __saturatef(c[4]) + w3 * __saturatef(c[6]);
    const float sy = w0 * __saturatef(c[1]) + w1 * __saturatef(c[3])
                   + w2 * __saturatef(c[5]) + w3 * __saturatef(c[7]);
    ((float2*)g_samples4)[tid] = make_float2(sx, sy);
}

__global__ __launch_bounds__(NT)
void glyph_kernel(float* __restrict__ out)
{
    __shared__ float2 keep[NS + 8];
    __shared__ float4 keep2_4[4 * K2ST];     // per-warp refiltered lists
    __shared__ float  wmin[4];
    __shared__ int    cnt[8];

    const int tid  = threadIdx.x;
    const int lane = tid & 31;
    const int w    = tid >> 5;

    // swizzled tile id: decorrelate spatial clusters from SM placement
    const int tile = (blockIdx.x * 997 + 311) & 2047;
    const int x0 = (tile & 31) * BX;
    const int y0 = (tile >> 5) * BY;

    const float inv = 1.0f / 511.0f;
    const float cx = ((float)x0 + 7.5f) * inv;
    const float cy = ((float)y0 + 3.5f) * inv;
    const float r  = 0.0162f + 1e-4f;        // 0.5*sqrt(15^2+7^2)/511

    // ---- load 2 samples per thread, center dist^2, block-min ----
    const float4 s4 = g_samples4[tid & (NS / 2 - 1)];
    float dx = cx - s4.x, dy = cy - s4.y;
    const float dc2A = fmaf(dx, dx, dy * dy);
    dx = cx - s4.z; dy = cy - s4.w;
    const float dc2B = fmaf(dx, dx, dy * dy);

    {
        const float m = fminf(dc2A, dc2B);
        const int rm = __reduce_min_sync(0xffffffffu, __float_as_int(m));
        if (lane == 0) wmin[w] = __int_as_float(rm);
    }
    __syncthreads();
    const float dcmin = sqrtf(fminf(fminf(wmin[0], wmin[1]), fminf(wmin[2], wmin[3])));

    const int px = x0 + (tid & 15);
    const int py = y0 + (tid >> 4);
    const int p  = py * SIZE + px;

    // ---- whole-block skip: coverage < 2.3e-5 ----
    if (dcmin > 0.115f + r) {
        out[p] = 1.0f;
        return;
    }

    // ---- block compaction: keep dc <= dcmin + 2r + 0.055 ----
    const float thr  = dcmin + 2.0f * r + 0.055f;
    const float thr2 = thr * thr;
    const bool kA = (dc2A <= thr2);
    const bool kB = (dc2B <= thr2);
    const unsigned mA = __ballot_sync(0xffffffffu, kA);
    const unsigned mB = __ballot_sync(0xffffffffu, kB);
    if (lane == 0) { cnt[2 * w] = __popc(mA); cnt[2 * w + 1] = __popc(mB); }
    __syncthreads();
    int off[9];
    off[0] = 0;
    #pragma unroll
    for (int i = 0; i < 8; i++) off[i + 1] = off[i] + cnt[i];
    const int n = off[8];
    const unsigned lt = (1u << lane) - 1u;
    if (kA) keep[off[2 * w]     + __popc(mA & lt)] = make_float2(s4.x, s4.y);
    if (kB) keep[off[2 * w + 1] + __popc(mB & lt)] = make_float2(s4.z, s4.w);
    __syncthreads();

    // ---- per-warp refilter: warp w covers pixel rows y0+2w..y0+2w+1 ----
    const float cyw = ((float)(y0 + 2 * w) + 0.5f) * inv;
    const float rw  = 0.014709f + 1e-4f;     // 0.5*sqrt(15^2+1)/511
    float2* kp = (float2*)(keep2_4 + w * K2ST);

    float mw = 1e30f;
    for (int i = lane; i < n; i += 32) {
        const float2 q = keep[i];
        const float ax = cx - q.x, ay = cyw - q.y;
        mw = fminf(mw, fmaf(ax, ax, ay * ay));
    }
    const int rmw = __reduce_min_sync(0xffffffffu, __float_as_int(mw));
    const float dwmin = sqrtf(__int_as_float(rmw));
    const float tw  = dwmin + 2.0f * rw + 0.05f;
    const float tw2 = tw * tw;

    int c = 0;
    for (int i0 = 0; i0 < n; i0 += 32) {
        const int i = i0 + lane;
        bool a = false;
        float2 q = make_float2(0.f, 0.f);
        if (i < n) {
            q = keep[i];
            const float ax = cx - q.x, ay = cyw - q.y;
            a = (fmaf(ax, ax, ay * ay) <= tw2);
        }
        const unsigned mm = __ballot_sync(0xffffffffu, a);
        if (a) kp[c + __popc(mm & lt)] = q;
        c += __popc(mm);
    }
    const int n2 = (c + 7) & ~7;
    if (lane < n2 - c) kp[c + lane] = make_float2(100.0f, 100.0f);  // sentinels
    __syncwarp();

    // ---- per-pixel single-pass soft-min ----
    const float gx = (float)px * inv;
    const float gy = (float)py * inv;
    const float NEGK = -369.3298503f;        // -256 * log2(e)
    const float4* kp4 = (const float4*)kp;
    float acc = 0.0f;
    #pragma unroll 4
    for (int i = 0; i < (n2 >> 1); i++) {
        const float4 q = kp4[i];
        float ax = gx - q.x, ay = gy - q.y;
        const float dA = fsqrt_approx(fmaf(ax, ax, ay * ay));
        ax = gx - q.z; ay = gy - q.w;
        const float dB = fsqrt_approx(fmaf(ax, ax, ay * ay));
        acc += fexp2_approx(dA * NEGK);
        acc += fexp2_approx(dB * NEGK);
    }

    const float md = flog2_approx(acc) * (-0.69314718f / 256.0f);
    const float z  = (0.04f - md) * (200.0f * 1.44269504f);
    out[p] = 1.0f / (1.0f + fexp2_approx(z));
}

extern "C" void kernel_launch(void* const* d_in, const int* in_sizes, int n_in,
                              void* d_out, int out_size) {
    const float* cp = (const float*)d_in[0];   // control_points [8,4,2]
    float* out = (float*)d_out;
    sample_kernel<<<1, NS>>>(cp);
    glyph_kernel<<<2048, NT>>>(out);
}

// round 6
// speedup vs baseline: 1.0049x; 1.0049x over previous
#include <cuda_runtime.h>

#define SIZE 512
#define NS 256
#define BX 16
#define BY 8
#define NT 128

__device__ float4 g_samples4[NS / 2];   // 256 float2 samples packed as float4

__device__ __forceinline__ float fsqrt_approx(float x) {
    float r; asm("sqrt.approx.f32 %0, %1;" : "=f"(r) : "f"(x)); return r;
}
__device__ __forceinline__ float fexp2_approx(float x) {
    float r; asm("ex2.approx.f32 %0, %1;" : "=f"(r) : "f"(x)); return r;
}
__device__ __forceinline__ float flog2_approx(float x) {
    float r; asm("lg2.approx.f32 %0, %1;" : "=f"(r) : "f"(x)); return r;
}

// ---- setup: compute the 256 clamped Bezier samples once ----
__global__ void sample_kernel(const float* __restrict__ cp) {
    const int tid = threadIdx.x;          // 0..255
    const int stroke = tid >> 5;
    const int j = tid & 31;
    const float t  = (float)j * (1.0f / 31.0f);
    const float mt = 1.0f - t;
    const float* c = cp + stroke * 8;
    const float w0 = mt * mt * mt;
    const float w1 = 3.0f * mt * mt * t;
    const float w2 = 3.0f * mt * t * t;
    const float w3 = t * t * t;
    const float sx = w0 * __saturatef(c[0]) + w1 * __saturatef(c[2])
                   + w2 * __saturatef(c[4]) + w3 * __saturatef(c[6]);
    const float sy = w0 * __saturatef(c[1]) + w1 * __saturatef(c[3])
                   + w2 * __saturatef(c[5]) + w3 * __saturatef(c[7]);
    ((float2*)g_samples4)[tid] = make_float2(sx, sy);
}

__global__ __launch_bounds__(NT)
void glyph_kernel(float* __restrict__ out)
{
    __shared__ float2 keep[NS + 4];       // float4-aligned (NS+4 even, base aligned)
    __shared__ float  wmin[4];
    __shared__ int    cnt[8];

    const int tid  = threadIdx.x;
    const int lane = tid & 31;
    const int w    = tid >> 5;

    // swizzled tile id: spread active tiles across SMs (kept from R4: occ 50->99%)
    const int tile = (blockIdx.x * 997 + 311) & 2047;
    const int x0 = (tile & 31) * BX;
    const int y0 = (tile >> 5) * BY;

    const float inv = 1.0f / 511.0f;
    const float cx = ((float)x0 + 7.5f) * inv;
    const float cy = ((float)y0 + 3.5f) * inv;
    const float r  = 0.0162f + 1e-4f;     // 0.5*sqrt(15^2+7^2)/511

    // ---- load 2 precomputed samples per thread, center dist^2, block-min ----
    const float4 s4 = g_samples4[tid];    // tid in 0..127 covers all 256 samples
    float dx = cx - s4.x, dy = cy - s4.y;
    const float dc2A = fmaf(dx, dx, dy * dy);
    dx = cx - s4.z; dy = cy - s4.w;
    const float dc2B = fmaf(dx, dx, dy * dy);

    {
        const int rm = __reduce_min_sync(0xffffffffu,
                                         __float_as_int(fminf(dc2A, dc2B)));
        if (lane == 0) wmin[w] = __int_as_float(rm);
    }
    __syncthreads();
    const float dcmin = sqrtf(fminf(fminf(wmin[0], wmin[1]), fminf(wmin[2], wmin[3])));

    const int px = x0 + (tid & 15);
    const int py = y0 + (tid >> 4);
    const int p  = py * SIZE + px;

    // ---- whole-block skip: coverage < 2.3e-5 ----
    if (dcmin > 0.115f + r) {
        out[p] = 1.0f;
        return;
    }

    // ---- block compaction: keep dc <= dcmin + 2r + 0.055 ----
    const float thr  = dcmin + 2.0f * r + 0.055f;
    const float thr2 = thr * thr;
    const bool kA = (dc2A <= thr2);
    const bool kB = (dc2B <= thr2);
    const unsigned mA = __ballot_sync(0xffffffffu, kA);
    const unsigned mB = __ballot_sync(0xffffffffu, kB);
    if (lane == 0) { cnt[2 * w] = __popc(mA); cnt[2 * w + 1] = __popc(mB); }
    __syncthreads();
    int off[9];
    off[0] = 0;
    #pragma unroll
    for (int i = 0; i < 8; i++) off[i + 1] = off[i] + cnt[i];
    const int n = off[8];
    const unsigned lt = (1u << lane) - 1u;
    if (kA) keep[off[2 * w]     + __popc(mA & lt)] = make_float2(s4.x, s4.y);
    if (kB) keep[off[2 * w + 1] + __popc(mB & lt)] = make_float2(s4.z, s4.w);
    if (tid < 4) keep[n + tid] = make_float2(100.0f, 100.0f);   // sentinels
    __syncthreads();
    const int n4 = (n + 3) & ~3;          // multiple of 4 samples = 2 float4

    // ---- per-pixel single-pass soft-min over compacted samples ----
    const float gx = (float)px * inv;
    const float gy = (float)py * inv;
    const float NEGK = -369.3298503f;     // -256 * log2(e)
    const float4* kp4 = (const float4*)keep;
    float acc = 0.0f;
    #pragma unroll 4
    for (int i = 0; i < (n4 >> 1); i++) {
        const float4 q = kp4[i];
        float ax = gx - q.x, ay = gy - q.y;
        const float dA = fsqrt_approx(fmaf(ax, ax, ay * ay));
        ax = gx - q.z; ay = gy - q.w;
        const float dB = fsqrt_approx(fmaf(ax, ax, ay * ay));
        acc += fexp2_approx(dA * NEGK);
        acc += fexp2_approx(dB * NEGK);
    }

    const float md = flog2_approx(acc) * (-0.69314718f / 256.0f);
    const float z  = (0.04f - md) * (200.0f * 1.44269504f);
    out[p] = 1.0f / (1.0f + fexp2_approx(z));
}

extern "C" void kernel_launch(void* const* d_in, const int* in_sizes, int n_in,
                              void* d_out, int out_size) {
    const float* cp = (const float*)d_in[0];   // control_points [8,4,2]
    float* out = (float*)d_out;
    sample_kernel<<<1, NS>>>(cp);
    glyph_kernel<<<2048, NT>>>(out);
}